// round 1
// baseline (speedup 1.0000x reference)
#include <cuda_runtime.h>
#include <math.h>
#include <stdint.h>

#define HIDDEN 4096
#define NH 32
#define NKV 8
#define HD 128
#define NB 2
#define SEQ 2048
#define NTOK (NB * SEQ)

// ---------------------------------------------------------------------------
// Scratch (device globals; no runtime allocation allowed)
// ---------------------------------------------------------------------------
__device__ float g_Q[(size_t)NTOK * NH * HD];    // 64 MB
__device__ float g_K[(size_t)NTOK * NKV * HD];   // 16 MB
__device__ float g_V[(size_t)NTOK * NKV * HD];   // 16 MB
__device__ float g_O[(size_t)NTOK * NH * HD];    // 64 MB

// ---------------------------------------------------------------------------
// NT GEMM: C[m][n] = sum_k A[m*K+k] * B[n*K+k]
// 128x128 tile, BK=16, 256 threads, 8x8 per-thread microtile.
// M,N,K must be multiples of 128/128/16 (true here: 4096/4096, 1024, 4096).
// ---------------------------------------------------------------------------
__global__ __launch_bounds__(256) void sgemm_nt(
    const float* __restrict__ A, const float* __restrict__ B,
    float* __restrict__ C, int M, int N, int K)
{
    __shared__ float As[16][128];
    __shared__ float Bs[16][128];

    const int tid = threadIdx.x;
    const int bm = blockIdx.y * 128;
    const int bn = blockIdx.x * 128;

    // loader mapping: each thread loads 8 consecutive floats of one tile row
    const int lr = tid >> 1;            // 0..127 (row within tile)
    const int lc = (tid & 1) << 3;      // 0 or 8 (col offset within BK=16)
    const float* Ap = A + (size_t)(bm + lr) * K + lc;
    const float* Bp = B + (size_t)(bn + lr) * K + lc;

    // compute mapping
    const int ty = tid >> 4;            // 0..15 -> rows ty*8..ty*8+7
    const int tx = tid & 15;            // 0..15 -> cols tx*8..tx*8+7

    float acc[8][8];
#pragma unroll
    for (int i = 0; i < 8; i++)
#pragma unroll
        for (int j = 0; j < 8; j++) acc[i][j] = 0.f;

    for (int k0 = 0; k0 < K; k0 += 16) {
        // prefetch into registers
        float4 a0 = *(const float4*)(Ap + k0);
        float4 a1 = *(const float4*)(Ap + k0 + 4);
        float4 b0 = *(const float4*)(Bp + k0);
        float4 b1 = *(const float4*)(Bp + k0 + 4);

        __syncthreads();   // previous compute done reading smem
        As[lc + 0][lr] = a0.x; As[lc + 1][lr] = a0.y;
        As[lc + 2][lr] = a0.z; As[lc + 3][lr] = a0.w;
        As[lc + 4][lr] = a1.x; As[lc + 5][lr] = a1.y;
        As[lc + 6][lr] = a1.z; As[lc + 7][lr] = a1.w;
        Bs[lc + 0][lr] = b0.x; Bs[lc + 1][lr] = b0.y;
        Bs[lc + 2][lr] = b0.z; Bs[lc + 3][lr] = b0.w;
        Bs[lc + 4][lr] = b1.x; Bs[lc + 5][lr] = b1.y;
        Bs[lc + 6][lr] = b1.z; Bs[lc + 7][lr] = b1.w;
        __syncthreads();

#pragma unroll
        for (int kk = 0; kk < 16; kk++) {
            float a[8], b[8];
            float4 av0 = *(const float4*)&As[kk][ty * 8];
            float4 av1 = *(const float4*)&As[kk][ty * 8 + 4];
            float4 bv0 = *(const float4*)&Bs[kk][tx * 8];
            float4 bv1 = *(const float4*)&Bs[kk][tx * 8 + 4];
            a[0] = av0.x; a[1] = av0.y; a[2] = av0.z; a[3] = av0.w;
            a[4] = av1.x; a[5] = av1.y; a[6] = av1.z; a[7] = av1.w;
            b[0] = bv0.x; b[1] = bv0.y; b[2] = bv0.z; b[3] = bv0.w;
            b[4] = bv1.x; b[5] = bv1.y; b[6] = bv1.z; b[7] = bv1.w;
#pragma unroll
            for (int i = 0; i < 8; i++)
#pragma unroll
                for (int j = 0; j < 8; j++)
                    acc[i][j] += a[i] * b[j];
        }
    }

#pragma unroll
    for (int i = 0; i < 8; i++) {
        float* cp = C + (size_t)(bm + ty * 8 + i) * N + bn + tx * 8;
        *(float4*)(cp + 0) = make_float4(acc[i][0], acc[i][1], acc[i][2], acc[i][3]);
        *(float4*)(cp + 4) = make_float4(acc[i][4], acc[i][5], acc[i][6], acc[i][7]);
    }
}

// ---------------------------------------------------------------------------
// RoPE in-place on [NTOK, nheads*128]; position = token % SEQ (== arange(S)).
// One thread per (token, head, j), j in 0..63: pair (j, j+64).
// ---------------------------------------------------------------------------
__global__ __launch_bounds__(256) void rope_kernel(float* __restrict__ X, int nheads)
{
    const size_t idx = (size_t)blockIdx.x * blockDim.x + threadIdx.x;
    const size_t total = (size_t)NTOK * nheads * 64;
    if (idx >= total) return;

    const int j = (int)(idx & 63);
    const size_t th = idx >> 6;               // token*nheads + head
    const int head = (int)(th % nheads);
    const size_t token = th / nheads;
    const int s = (int)(token % SEQ);

    // inv_freq = 10000^(-j/64)
    const float inv = __expf(-(float)j * (9.210340371976184f / 64.0f)); // ln(10000)=9.2103...
    const float ang = (float)s * inv;
    float c, sn;
    __sincosf(ang, &sn, &c);
    // use precise versions for large-angle accuracy
    c = cosf(ang);
    sn = sinf(ang);

    float* base = X + token * (size_t)(nheads * HD) + (size_t)head * HD;
    const float x1 = base[j];
    const float x2 = base[j + 64];
    base[j]      = x1 * c - x2 * sn;
    base[j + 64] = x2 * c + x1 * sn;
}

// ---------------------------------------------------------------------------
// Flash attention (non-causal, full softmax over SEQ keys).
// grid = (SEQ/64, NH, NB), 256 threads.
// smem: Qs[64][132], KVs[64][132] (K then reused for V), Ss[64][65].
// Each thread owns one query row (row = tid>>2) x 32 interleaved d-lanes
// (d = (tid&3) + 4k) of the output accumulator -> conflict-free V reads.
// ---------------------------------------------------------------------------
#define QS_STRIDE 132
#define SS_STRIDE 65
#define ATT_SMEM_FLOATS (2 * 64 * QS_STRIDE + 64 * SS_STRIDE)
#define ATT_SMEM_BYTES (ATT_SMEM_FLOATS * 4)

__global__ __launch_bounds__(256) void attn_kernel(
    const float* __restrict__ Q, const float* __restrict__ K,
    const float* __restrict__ V, float* __restrict__ O)
{
    extern __shared__ float sm[];
    float* Qs  = sm;                       // [64][132]
    float* KVs = sm + 64 * QS_STRIDE;      // [64][132]
    float* Ss  = sm + 2 * 64 * QS_STRIDE;  // [64][65]

    const int tid = threadIdx.x;
    const int qt = blockIdx.x;     // query tile
    const int h  = blockIdx.y;     // q head
    const int b  = blockIdx.z;     // batch
    const int kvh = h >> 2;        // N_GROUPS = 4

    const float* Qbase = Q + ((size_t)(b * SEQ + qt * 64)) * (NH * HD) + (size_t)h * HD;
    const float* Kbase = K + ((size_t)b * SEQ) * (NKV * HD) + (size_t)kvh * HD;
    const float* Vbase = V + ((size_t)b * SEQ) * (NKV * HD) + (size_t)kvh * HD;

    // load Q tile (64 rows x 128), row stride NH*HD
    for (int i = tid; i < 64 * 32; i += 256) {
        const int r = i >> 5;
        const int c = (i & 31) * 4;
        float4 v = *(const float4*)(Qbase + (size_t)r * (NH * HD) + c);
        float* dst = Qs + r * QS_STRIDE + c;
        dst[0] = v.x; dst[1] = v.y; dst[2] = v.z; dst[3] = v.w;
    }

    const int row = tid >> 2;   // 0..63: query row owned for softmax/output
    const int dch = tid & 3;    // d-lane interleave
    const int ty = tid >> 4;    // score microtile row group
    const int tx = tid & 15;    // score microtile col group

    float o[32];
#pragma unroll
    for (int k = 0; k < 32; k++) o[k] = 0.f;
    float mrow = -1e30f;
    float lrow = 0.f;

    for (int j0 = 0; j0 < SEQ; j0 += 64) {
        __syncthreads();  // previous accumulation done reading KVs (Q visible after 1st)

        // load K tile
        for (int i = tid; i < 64 * 32; i += 256) {
            const int r = i >> 5;
            const int c = (i & 31) * 4;
            float4 v = *(const float4*)(Kbase + (size_t)(j0 + r) * (NKV * HD) + c);
            float* dst = KVs + r * QS_STRIDE + c;
            dst[0] = v.x; dst[1] = v.y; dst[2] = v.z; dst[3] = v.w;
        }
        __syncthreads();

        // scores: each thread computes 4x4 of the 64x64 tile
        float acc[4][4];
#pragma unroll
        for (int i = 0; i < 4; i++)
#pragma unroll
            for (int j = 0; j < 4; j++) acc[i][j] = 0.f;

#pragma unroll 4
        for (int d4 = 0; d4 < 32; d4++) {
            float4 aa[4], bb[4];
#pragma unroll
            for (int i = 0; i < 4; i++)
                aa[i] = *(const float4*)(Qs + (ty * 4 + i) * QS_STRIDE + d4 * 4);
#pragma unroll
            for (int j = 0; j < 4; j++)
                bb[j] = *(const float4*)(KVs + (tx * 4 + j) * QS_STRIDE + d4 * 4);
#pragma unroll
            for (int i = 0; i < 4; i++)
#pragma unroll
                for (int j = 0; j < 4; j++) {
                    acc[i][j] += aa[i].x * bb[j].x;
                    acc[i][j] += aa[i].y * bb[j].y;
                    acc[i][j] += aa[i].z * bb[j].z;
                    acc[i][j] += aa[i].w * bb[j].w;
                }
        }
        const float scale = 0.08838834764831845f;  // 1/sqrt(128)
#pragma unroll
        for (int i = 0; i < 4; i++)
#pragma unroll
            for (int j = 0; j < 4; j++)
                Ss[(ty * 4 + i) * SS_STRIDE + tx * 4 + j] = acc[i][j] * scale;
        __syncthreads();  // scores visible; K reads done

        // load V tile into KVs (overlaps with row-stat computation below)
        for (int i = tid; i < 64 * 32; i += 256) {
            const int r = i >> 5;
            const int c = (i & 31) * 4;
            float4 v = *(const float4*)(Vbase + (size_t)(j0 + r) * (NKV * HD) + c);
            float* dst = KVs + r * QS_STRIDE + c;
            dst[0] = v.x; dst[1] = v.y; dst[2] = v.z; dst[3] = v.w;
        }

        // online softmax row stats (reads Ss only)
        const float* srow = Ss + row * SS_STRIDE;
        float mj = -1e30f;
#pragma unroll 8
        for (int c = 0; c < 64; c++) mj = fmaxf(mj, srow[c]);
        const float mn = fmaxf(mrow, mj);
        const float corr = __expf(mrow - mn);
        lrow *= corr;
#pragma unroll
        for (int k = 0; k < 32; k++) o[k] *= corr;
        mrow = mn;

        __syncthreads();  // V visible

        // accumulate O += P * V
        for (int c = 0; c < 64; c++) {
            const float p = __expf(srow[c] - mn);
            lrow += p;
            const float* vr = KVs + c * QS_STRIDE + dch;
#pragma unroll
            for (int k = 0; k < 32; k++) o[k] += p * vr[4 * k];
        }
    }

    const float invl = 1.f / lrow;
    float* Obase = O + ((size_t)(b * SEQ + qt * 64 + row)) * (NH * HD) + (size_t)h * HD + dch;
#pragma unroll
    for (int k = 0; k < 32; k++) Obase[4 * k] = o[k] * invl;
}

// ---------------------------------------------------------------------------
// Launch
// ---------------------------------------------------------------------------
extern "C" void kernel_launch(void* const* d_in, const int* in_sizes, int n_in,
                              void* d_out, int out_size)
{
    const float* hs = (const float*)d_in[0];
    // d_in[1] = position_ids (values are arange(S); recomputed on device instead)
    const float* Wq = (const float*)d_in[2];
    const float* Wk = (const float*)d_in[3];
    const float* Wv = (const float*)d_in[4];
    const float* Wo = (const float*)d_in[5];
    float* out = (float*)d_out;

    static float *Qp = nullptr, *Kp = nullptr, *Vp = nullptr, *Op = nullptr;
    static bool inited = false;
    if (!inited) {
        cudaGetSymbolAddress((void**)&Qp, g_Q);
        cudaGetSymbolAddress((void**)&Kp, g_K);
        cudaGetSymbolAddress((void**)&Vp, g_V);
        cudaGetSymbolAddress((void**)&Op, g_O);
        cudaFuncSetAttribute(attn_kernel,
                             cudaFuncAttributeMaxDynamicSharedMemorySize,
                             ATT_SMEM_BYTES);
        inited = true;
    }

    const int M = NTOK;  // 4096 token rows
    dim3 blk(256);

    // Projections (NT GEMMs)
    sgemm_nt<<<dim3(HIDDEN / 128, M / 128), blk>>>(hs, Wq, Qp, M, HIDDEN, HIDDEN);
    sgemm_nt<<<dim3((NKV * HD) / 128, M / 128), blk>>>(hs, Wk, Kp, M, NKV * HD, HIDDEN);
    sgemm_nt<<<dim3((NKV * HD) / 128, M / 128), blk>>>(hs, Wv, Vp, M, NKV * HD, HIDDEN);

    // RoPE on Q and K
    {
        const size_t tq = (size_t)M * NH * 64;
        const size_t tk = (size_t)M * NKV * 64;
        rope_kernel<<<(unsigned)((tq + 255) / 256), 256>>>(Qp, NH);
        rope_kernel<<<(unsigned)((tk + 255) / 256), 256>>>(Kp, NKV);
    }

    // Attention
    attn_kernel<<<dim3(SEQ / 64, NH, NB), 256, ATT_SMEM_BYTES>>>(Qp, Kp, Vp, Op);

    // Output projection
    sgemm_nt<<<dim3(HIDDEN / 128, M / 128), blk>>>(Op, Wo, out, M, HIDDEN, HIDDEN);
}

// round 4
// speedup vs baseline: 1.4366x; 1.4366x over previous
#include <cuda_runtime.h>
#include <cuda_bf16.h>
#include <math.h>
#include <stdint.h>

#define HIDDEN 4096
#define NH 32
#define NKV 8
#define HD 128
#define NB 2
#define SEQ 2048
#define NTOK (NB * SEQ)
#define K2 (3 * HIDDEN)   // expanded K for bf16x3 split: 12288

// ---------------------------------------------------------------------------
// Scratch (device globals; no runtime allocation allowed)
// ---------------------------------------------------------------------------
__device__ float g_Q[(size_t)NTOK * NH * HD];
__device__ float g_K[(size_t)NTOK * NKV * HD];
__device__ float g_V[(size_t)NTOK * NKV * HD];
__device__ float g_O[(size_t)NTOK * NH * HD];

__device__ __align__(256) __nv_bfloat16 g_hs2[(size_t)NTOK * K2];      // A-layout [h,l,h]
__device__ __align__(256) __nv_bfloat16 g_O2 [(size_t)NTOK * K2];      // A-layout
__device__ __align__(256) __nv_bfloat16 g_Wq2[(size_t)HIDDEN * K2];    // B-layout [h,h,l]
__device__ __align__(256) __nv_bfloat16 g_Wk2[(size_t)(NKV*HD) * K2];
__device__ __align__(256) __nv_bfloat16 g_Wv2[(size_t)(NKV*HD) * K2];
__device__ __align__(256) __nv_bfloat16 g_Wo2[(size_t)HIDDEN * K2];

// ---------------------------------------------------------------------------
// Base-target PTX helpers (NO 'a'-features: no tcgen05/TMEM/cta_group)
// ---------------------------------------------------------------------------
__device__ __forceinline__ uint32_t smem_u32(const void* p) {
    uint32_t a;
    asm("{ .reg .u64 t; cvta.to.shared.u64 t, %1; cvt.u32.u64 %0, t; }"
        : "=r"(a) : "l"(p));
    return a;
}
__device__ __forceinline__ void cp16(uint32_t dst, const void* src) {
    asm volatile("cp.async.cg.shared.global [%0], [%1], 16;"
                 :: "r"(dst), "l"(src) : "memory");
}
__device__ __forceinline__ void cp_commit() {
    asm volatile("cp.async.commit_group;" ::: "memory");
}
__device__ __forceinline__ void cp_wait1() {
    asm volatile("cp.async.wait_group 1;" ::: "memory");
}
__device__ __forceinline__ void cp_wait0() {
    asm volatile("cp.async.wait_group 0;" ::: "memory");
}
__device__ __forceinline__ void ldm_x4(uint32_t& r0, uint32_t& r1, uint32_t& r2,
                                       uint32_t& r3, uint32_t addr) {
    asm volatile("ldmatrix.sync.aligned.m8n8.x4.shared.b16 {%0,%1,%2,%3}, [%4];"
                 : "=r"(r0), "=r"(r1), "=r"(r2), "=r"(r3) : "r"(addr));
}
__device__ __forceinline__ void mma_bf16(float* c, uint32_t a0, uint32_t a1,
                                         uint32_t a2, uint32_t a3,
                                         uint32_t b0, uint32_t b1) {
    asm volatile("mma.sync.aligned.m16n8k16.row.col.f32.bf16.bf16.f32 "
                 "{%0,%1,%2,%3}, {%4,%5,%6,%7}, {%8,%9}, {%0,%1,%2,%3};"
                 : "+f"(c[0]), "+f"(c[1]), "+f"(c[2]), "+f"(c[3])
                 : "r"(a0), "r"(a1), "r"(a2), "r"(a3), "r"(b0), "r"(b1));
}

// ---------------------------------------------------------------------------
// fp32 -> bf16x3 expansion.
// A-layout: [hi | lo | hi]   B-layout: [hi | hi | lo]
// Pairing over K''=3K gives Ah*Bh + Al*Bh + Ah*Bl (drops only Al*Bl ~2^-18).
// ---------------------------------------------------------------------------
template <bool ALAYOUT>
__global__ __launch_bounds__(256) void conv_split(const float* __restrict__ X,
                                                  __nv_bfloat16* __restrict__ Y,
                                                  int K, size_t total4)
{
    size_t idx = (size_t)blockIdx.x * blockDim.x + threadIdx.x;
    if (idx >= total4) return;
    const int kq = (int)(idx % (size_t)(K / 4));
    const size_t r = idx / (size_t)(K / 4);
    const int k = kq * 4;

    float4 v = *(const float4*)(X + r * (size_t)K + k);
    __nv_bfloat16 h0 = __float2bfloat16_rn(v.x);
    __nv_bfloat16 h1 = __float2bfloat16_rn(v.y);
    __nv_bfloat16 h2 = __float2bfloat16_rn(v.z);
    __nv_bfloat16 h3 = __float2bfloat16_rn(v.w);
    __nv_bfloat16 l0 = __float2bfloat16_rn(v.x - __bfloat162float(h0));
    __nv_bfloat16 l1 = __float2bfloat16_rn(v.y - __bfloat162float(h1));
    __nv_bfloat16 l2 = __float2bfloat16_rn(v.z - __bfloat162float(h2));
    __nv_bfloat16 l3 = __float2bfloat16_rn(v.w - __bfloat162float(h3));

    __nv_bfloat162 hA = __nv_bfloat162(h0, h1), hB = __nv_bfloat162(h2, h3);
    __nv_bfloat162 lA = __nv_bfloat162(l0, l1), lB = __nv_bfloat162(l2, l3);

    __nv_bfloat16* out = Y + r * (size_t)(3 * K);
    __nv_bfloat162* p0 = (__nv_bfloat162*)(out + k);
    __nv_bfloat162* p1 = (__nv_bfloat162*)(out + K + k);
    __nv_bfloat162* p2 = (__nv_bfloat162*)(out + 2 * K + k);
    p0[0] = hA; p0[1] = hB;
    if (ALAYOUT) { p1[0] = lA; p1[1] = lB; p2[0] = hA; p2[1] = hB; }
    else         { p1[0] = hA; p1[1] = hB; p2[0] = lA; p2[1] = lB; }
}

// ---------------------------------------------------------------------------
// bf16 NT GEMM via mma.sync (HMMA, base sm_80 feature set).
// C[m][n] = sum_k A[m*K2+k] * B[n*K2+k], fp32 accum.
// CTA tile 128x128, BK=32, 3-stage cp.async pipeline.
// smem row stride 40 bf16 = 80 B: 8 consecutive rows at 80B stride cover all
// 32 banks exactly once -> conflict-free ldmatrix.
// Warps: 2(m) x 4(n); warp tile 64x32 = 4 m16-tiles x 4 n8-tiles.
//
// Fragment mapping (PTX ISA m16n8k16.row.col):
//   A (16x16 row-major, smem [m][k]): ldmatrix.x4,
//     addr = &A[lane%16][(lane/16)*8]  -> regs a0..a3 in mma order.
//   B (8x16, smem [n][k] == col-major KxN): ldmatrix.x4 over two n8-tiles,
//     quad=lane/8: addr = &B[(quad>>1)*8 + lane%8][(quad&1)*8]
//     -> regs {b0,b1} tile0, {b2,b3} tile1.
// ---------------------------------------------------------------------------
#define GBK 32
#define GNC (K2 / GBK)          // 384 chunks
#define AST 40                  // smem stride in bf16 (80 bytes)
#define ASTG 10240              // 128*80 bytes per A stage
#define BSTG 10240
#define B_BASE (3 * ASTG)       // B stages start after 3 A stages
#define GEMM_SMEM (6 * 10240)   // 61440 bytes

__device__ __forceinline__ void gemm_compute_chunk(
    uint32_t sb, int s, int wm0, int wn0,
    uint32_t laneA_off, uint32_t laneB_off, float acc[4][4][4])
{
    const uint32_t Ab = sb + s * ASTG;
    const uint32_t Bb = sb + B_BASE + s * BSTG;
#pragma unroll
    for (int ks = 0; ks < 2; ks++) {
        uint32_t af[4][4];
#pragma unroll
        for (int mt = 0; mt < 4; mt++) {
            ldm_x4(af[mt][0], af[mt][1], af[mt][2], af[mt][3],
                   Ab + (uint32_t)((wm0 + mt * 16) * 80 + ks * 32) + laneA_off);
        }
        uint32_t bf[2][4];
#pragma unroll
        for (int ntp = 0; ntp < 2; ntp++) {
            ldm_x4(bf[ntp][0], bf[ntp][1], bf[ntp][2], bf[ntp][3],
                   Bb + (uint32_t)((wn0 + ntp * 16) * 80 + ks * 32) + laneB_off);
        }
#pragma unroll
        for (int mt = 0; mt < 4; mt++)
#pragma unroll
            for (int nt = 0; nt < 4; nt++)
                mma_bf16(acc[mt][nt], af[mt][0], af[mt][1], af[mt][2], af[mt][3],
                         bf[nt >> 1][(nt & 1) * 2], bf[nt >> 1][(nt & 1) * 2 + 1]);
    }
}

__global__ __launch_bounds__(256)
void gemm_mma(const __nv_bfloat16* __restrict__ A,
              const __nv_bfloat16* __restrict__ B,
              float* __restrict__ C, int N)
{
    extern __shared__ char smem[];
    const uint32_t sb = smem_u32(smem);
    const int tid = threadIdx.x;
    const int wid = tid >> 5;
    const int lane = tid & 31;
    const int bm = blockIdx.y * 128;
    const int bn = blockIdx.x * 128;

    // loader: thread handles 16B chunk idx=tid (row tid/4, c8=tid%4) and idx+256
    const int lr = tid >> 2, lc8 = tid & 3;
    const __nv_bfloat16* gA0 = A + (size_t)(bm + lr) * K2 + lc8 * 8;
    const __nv_bfloat16* gA1 = gA0 + (size_t)64 * K2;
    const __nv_bfloat16* gB0 = B + (size_t)(bn + lr) * K2 + lc8 * 8;
    const __nv_bfloat16* gB1 = gB0 + (size_t)64 * K2;
    const uint32_t sA0 = (uint32_t)(lr * 80 + lc8 * 16);
    const uint32_t sA1 = sA0 + 64 * 80;

#define GLOAD(c, s)                                                   \
    {                                                                 \
        const size_t kofs = (size_t)(c) * GBK;                        \
        cp16(sb + (s) * ASTG + sA0, gA0 + kofs);                      \
        cp16(sb + (s) * ASTG + sA1, gA1 + kofs);                      \
        cp16(sb + B_BASE + (s) * BSTG + sA0, gB0 + kofs);             \
        cp16(sb + B_BASE + (s) * BSTG + sA1, gB1 + kofs);             \
        cp_commit();                                                  \
    }

    GLOAD(0, 0);
    GLOAD(1, 1);

    const int wm0 = (wid & 1) * 64;
    const int wn0 = (wid >> 1) * 32;
    const uint32_t laneA_off = (uint32_t)((lane & 15) * 80 + (lane >> 4) * 16);
    const int quad = lane >> 3;
    const uint32_t laneB_off =
        (uint32_t)((((quad >> 1) * 8) + (lane & 7)) * 80 + (quad & 1) * 16);

    float acc[4][4][4];
#pragma unroll
    for (int mt = 0; mt < 4; mt++)
#pragma unroll
        for (int nt = 0; nt < 4; nt++)
#pragma unroll
            for (int q = 0; q < 4; q++) acc[mt][nt][q] = 0.f;

    for (int c = 0; c < GNC - 1; c++) {
        cp_wait1();            // chunk c resident (<=1 group pending)
        __syncthreads();       // visible to all warps
        gemm_compute_chunk(sb, c % 3, wm0, wn0, laneA_off, laneB_off, acc);
        if (c + 2 < GNC) GLOAD(c + 2, (c + 2) % 3);
    }
    cp_wait0();                // final chunk resident
    __syncthreads();
    gemm_compute_chunk(sb, (GNC - 1) % 3, wm0, wn0, laneA_off, laneB_off, acc);
#undef GLOAD

    // Epilogue: c0,c1 -> (row g, col q*2..+1); c2,c3 -> row g+8
    const int g = lane >> 2;
    const int q = lane & 3;
#pragma unroll
    for (int mt = 0; mt < 4; mt++) {
        const size_t row = (size_t)(bm + wm0 + mt * 16 + g);
#pragma unroll
        for (int nt = 0; nt < 4; nt++) {
            const int col = bn + wn0 + nt * 8 + q * 2;
            *(float2*)(C + row * N + col) =
                make_float2(acc[mt][nt][0], acc[mt][nt][1]);
            *(float2*)(C + (row + 8) * N + col) =
                make_float2(acc[mt][nt][2], acc[mt][nt][3]);
        }
    }
}

// ---------------------------------------------------------------------------
// RoPE in-place on [NTOK, nheads*128]; position = token % SEQ.
// ---------------------------------------------------------------------------
__global__ __launch_bounds__(256) void rope_kernel(float* __restrict__ X, int nheads)
{
    const size_t idx = (size_t)blockIdx.x * blockDim.x + threadIdx.x;
    const size_t total = (size_t)NTOK * nheads * 64;
    if (idx >= total) return;

    const int j = (int)(idx & 63);
    const size_t th = idx >> 6;
    const int head = (int)(th % nheads);
    const size_t token = th / nheads;
    const int s = (int)(token % SEQ);

    const float inv = __expf(-(float)j * (9.210340371976184f / 64.0f));
    const float ang = (float)s * inv;
    const float c = cosf(ang);
    const float sn = sinf(ang);

    float* base = X + token * (size_t)(nheads * HD) + (size_t)head * HD;
    const float x1 = base[j];
    const float x2 = base[j + 64];
    base[j]      = x1 * c - x2 * sn;
    base[j + 64] = x2 * c + x1 * sn;
}

// ---------------------------------------------------------------------------
// Flash attention (non-causal). grid = (SEQ/64, NH, NB), 256 threads.
// PV path uses float4 interleave: thread owns d = {16k + 4*dch + 0..3}.
// ---------------------------------------------------------------------------
#define QS_STRIDE 132
#define SS_STRIDE 65
#define ATT_SMEM_BYTES ((2 * 64 * QS_STRIDE + 64 * SS_STRIDE) * 4)

__global__ __launch_bounds__(256) void attn_kernel(
    const float* __restrict__ Q, const float* __restrict__ K,
    const float* __restrict__ V, float* __restrict__ O)
{
    extern __shared__ float sm[];
    float* Qs  = sm;
    float* KVs = sm + 64 * QS_STRIDE;
    float* Ss  = sm + 2 * 64 * QS_STRIDE;

    const int tid = threadIdx.x;
    const int qt = blockIdx.x;
    const int h  = blockIdx.y;
    const int b  = blockIdx.z;
    const int kvh = h >> 2;

    const float* Qbase = Q + ((size_t)(b * SEQ + qt * 64)) * (NH * HD) + (size_t)h * HD;
    const float* Kbase = K + ((size_t)b * SEQ) * (NKV * HD) + (size_t)kvh * HD;
    const float* Vbase = V + ((size_t)b * SEQ) * (NKV * HD) + (size_t)kvh * HD;

    for (int i = tid; i < 64 * 32; i += 256) {
        const int r = i >> 5;
        const int c = (i & 31) * 4;
        float4 v = *(const float4*)(Qbase + (size_t)r * (NH * HD) + c);
        *(float4*)(Qs + r * QS_STRIDE + c) = v;
    }

    const int row = tid >> 2;
    const int dch = tid & 3;
    const int ty = tid >> 4;
    const int tx = tid & 15;

    float4 o4[8];
#pragma unroll
    for (int k = 0; k < 8; k++) o4[k] = make_float4(0.f, 0.f, 0.f, 0.f);
    float mrow = -1e30f;
    float lrow = 0.f;

    for (int j0 = 0; j0 < SEQ; j0 += 64) {
        __syncthreads();
        for (int i = tid; i < 64 * 32; i += 256) {
            const int r = i >> 5;
            const int c = (i & 31) * 4;
            float4 v = *(const float4*)(Kbase + (size_t)(j0 + r) * (NKV * HD) + c);
            *(float4*)(KVs + r * QS_STRIDE + c) = v;
        }
        __syncthreads();

        float acc[4][4];
#pragma unroll
        for (int i = 0; i < 4; i++)
#pragma unroll
            for (int j = 0; j < 4; j++) acc[i][j] = 0.f;

#pragma unroll 4
        for (int d4 = 0; d4 < 32; d4++) {
            float4 aa[4], bb[4];
#pragma unroll
            for (int i = 0; i < 4; i++)
                aa[i] = *(const float4*)(Qs + (ty * 4 + i) * QS_STRIDE + d4 * 4);
#pragma unroll
            for (int j = 0; j < 4; j++)
                bb[j] = *(const float4*)(KVs + (tx * 4 + j) * QS_STRIDE + d4 * 4);
#pragma unroll
            for (int i = 0; i < 4; i++)
#pragma unroll
                for (int j = 0; j < 4; j++) {
                    acc[i][j] += aa[i].x * bb[j].x;
                    acc[i][j] += aa[i].y * bb[j].y;
                    acc[i][j] += aa[i].z * bb[j].z;
                    acc[i][j] += aa[i].w * bb[j].w;
                }
        }
        const float scale = 0.08838834764831845f;
#pragma unroll
        for (int i = 0; i < 4; i++)
#pragma unroll
            for (int j = 0; j < 4; j++)
                Ss[(ty * 4 + i) * SS_STRIDE + tx * 4 + j] = acc[i][j] * scale;
        __syncthreads();

        for (int i = tid; i < 64 * 32; i += 256) {
            const int r = i >> 5;
            const int c = (i & 31) * 4;
            float4 v = *(const float4*)(Vbase + (size_t)(j0 + r) * (NKV * HD) + c);
            *(float4*)(KVs + r * QS_STRIDE + c) = v;
        }

        const float* srow = Ss + row * SS_STRIDE;
        float mj = -1e30f;
#pragma unroll 8
        for (int c = 0; c < 64; c++) mj = fmaxf(mj, srow[c]);
        const float mn = fmaxf(mrow, mj);
        const float corr = __expf(mrow - mn);
        lrow *= corr;
#pragma unroll
        for (int k = 0; k < 8; k++) {
            o4[k].x *= corr; o4[k].y *= corr; o4[k].z *= corr; o4[k].w *= corr;
        }
        mrow = mn;

        __syncthreads();

        for (int c = 0; c < 64; c++) {
            const float p = __expf(srow[c] - mn);
            lrow += p;
            const float4* vr = (const float4*)(KVs + c * QS_STRIDE) + dch;
#pragma unroll
            for (int k = 0; k < 8; k++) {
                float4 v = vr[k * 4];
                o4[k].x += p * v.x; o4[k].y += p * v.y;
                o4[k].z += p * v.z; o4[k].w += p * v.w;
            }
        }
    }

    const float invl = 1.f / lrow;
    float* Obase = O + ((size_t)(b * SEQ + qt * 64 + row)) * (NH * HD) + (size_t)h * HD + dch * 4;
#pragma unroll
    for (int k = 0; k < 8; k++) {
        *(float4*)(Obase + 16 * k) = make_float4(o4[k].x * invl, o4[k].y * invl,
                                                 o4[k].z * invl, o4[k].w * invl);
    }
}

// ---------------------------------------------------------------------------
// Launch
// ---------------------------------------------------------------------------
extern "C" void kernel_launch(void* const* d_in, const int* in_sizes, int n_in,
                              void* d_out, int out_size)
{
    const float* hs = (const float*)d_in[0];
    const float* Wq = (const float*)d_in[2];
    const float* Wk = (const float*)d_in[3];
    const float* Wv = (const float*)d_in[4];
    const float* Wo = (const float*)d_in[5];
    float* out = (float*)d_out;

    static float *Qp, *Kp, *Vp, *Op;
    static __nv_bfloat16 *hs2, *O2, *Wq2, *Wk2, *Wv2, *Wo2;
    static bool inited = false;
    if (!inited) {
        cudaGetSymbolAddress((void**)&Qp, g_Q);
        cudaGetSymbolAddress((void**)&Kp, g_K);
        cudaGetSymbolAddress((void**)&Vp, g_V);
        cudaGetSymbolAddress((void**)&Op, g_O);
        cudaGetSymbolAddress((void**)&hs2, g_hs2);
        cudaGetSymbolAddress((void**)&O2, g_O2);
        cudaGetSymbolAddress((void**)&Wq2, g_Wq2);
        cudaGetSymbolAddress((void**)&Wk2, g_Wk2);
        cudaGetSymbolAddress((void**)&Wv2, g_Wv2);
        cudaGetSymbolAddress((void**)&Wo2, g_Wo2);
        cudaFuncSetAttribute(attn_kernel,
                             cudaFuncAttributeMaxDynamicSharedMemorySize, ATT_SMEM_BYTES);
        cudaFuncSetAttribute(gemm_mma,
                             cudaFuncAttributeMaxDynamicSharedMemorySize, GEMM_SMEM);
        inited = true;
    }

    const int M = NTOK;  // 4096

    // Expand operands to bf16x3
    {
        const size_t t_hs = (size_t)M * HIDDEN / 4;
        const size_t t_wq = (size_t)HIDDEN * HIDDEN / 4;
        const size_t t_wk = (size_t)(NKV * HD) * HIDDEN / 4;
        conv_split<true ><<<(unsigned)((t_hs + 255) / 256), 256>>>(hs, hs2, HIDDEN, t_hs);
        conv_split<false><<<(unsigned)((t_wq + 255) / 256), 256>>>(Wq, Wq2, HIDDEN, t_wq);
        conv_split<false><<<(unsigned)((t_wk + 255) / 256), 256>>>(Wk, Wk2, HIDDEN, t_wk);
        conv_split<false><<<(unsigned)((t_wk + 255) / 256), 256>>>(Wv, Wv2, HIDDEN, t_wk);
        conv_split<false><<<(unsigned)((t_wq + 255) / 256), 256>>>(Wo, Wo2, HIDDEN, t_wq);
    }

    // Projections (HMMA)
    gemm_mma<<<dim3(HIDDEN / 128, M / 128), 256, GEMM_SMEM>>>(hs2, Wq2, Qp, HIDDEN);
    gemm_mma<<<dim3((NKV * HD) / 128, M / 128), 256, GEMM_SMEM>>>(hs2, Wk2, Kp, NKV * HD);
    gemm_mma<<<dim3((NKV * HD) / 128, M / 128), 256, GEMM_SMEM>>>(hs2, Wv2, Vp, NKV * HD);

    // RoPE
    {
        const size_t tq = (size_t)M * NH * 64;
        const size_t tk = (size_t)M * NKV * 64;
        rope_kernel<<<(unsigned)((tq + 255) / 256), 256>>>(Qp, NH);
        rope_kernel<<<(unsigned)((tk + 255) / 256), 256>>>(Kp, NKV);
    }

    // Attention
    attn_kernel<<<dim3(SEQ / 64, NH, NB), 256, ATT_SMEM_BYTES>>>(Qp, Kp, Vp, Op);

    // Output projection
    {
        const size_t t_o = (size_t)M * HIDDEN / 4;
        conv_split<true><<<(unsigned)((t_o + 255) / 256), 256>>>(Op, O2, HIDDEN, t_o);
        gemm_mma<<<dim3(HIDDEN / 128, M / 128), 256, GEMM_SMEM>>>(O2, Wo2, out, HIDDEN);
    }
}